// round 8
// baseline (speedup 1.0000x reference)
#include <cuda_runtime.h>
#include <float.h>

typedef unsigned long long ull;
#define FULLMASK 0xFFFFFFFFu

// ---------------------------------------------------------------------------
// MID_LOSS: B=8192, E=512, M=8, C=14, BETA=0.3
// x [B, E*M] f32 (m contiguous per e), y [B,C] i32, w [E,C] f32
// Design: warp-autonomous. 296 blocks x 128 thr = 1184 warps, one wave.
// Each warp owns samples s = gwarp + 1184*k. No __syncthreads in hot loop.
// Lane split: chalf = lane>>4 picks classes [0..6] or [7..13];
//             esub = lane&15 picks e-pair (2*esub, 2*esub+1) + 32*i, i<16.
// Accumulators packed over the e-pair -> w operand is a raw LDS.64.
// ---------------------------------------------------------------------------

static __device__ float g_partials[1184];

__device__ __forceinline__ ull ffma2(ull a, ull b, ull c) {
    ull d; asm("fma.rn.f32x2 %0, %1, %2, %3;" : "=l"(d) : "l"(a), "l"(b), "l"(c));
    return d;
}
__device__ __forceinline__ ull add2(ull a, ull b) {
    ull d; asm("add.rn.f32x2 %0, %1, %2;" : "=l"(d) : "l"(a), "l"(b));
    return d;
}
__device__ __forceinline__ ull mul2(ull a, ull b) {
    ull d; asm("mul.rn.f32x2 %0, %1, %2;" : "=l"(d) : "l"(a), "l"(b));
    return d;
}
__device__ __forceinline__ ull pk(float lo, float hi) {
    ull d; asm("mov.b64 %0, {%1, %2};" : "=l"(d) : "f"(lo), "f"(hi));
    return d;
}
__device__ __forceinline__ void upk(ull v, float& lo, float& hi) {
    asm("mov.b64 {%0, %1}, %2;" : "=f"(lo), "=f"(hi) : "l"(v));
}
__device__ __forceinline__ float softplus_f(float v) {
    return fmaxf(v, 0.0f) + log1pf(expf(-fabsf(v)));
}

__global__ __launch_bounds__(128) void main_kernel(const float* __restrict__ x,
                                                   const int*   __restrict__ y,
                                                   const float* __restrict__ w) {
    __shared__ __align__(16) float w_s[14 * 512];   // [c][e] transposed
    __shared__ float gram_s[196];
    __shared__ float dot_s[4][112];                 // per-warp [c][m]
    __shared__ float dc_s[4][16];                   // per-warp column maxes
    __shared__ float l1_s[4][2];

    const int tid   = threadIdx.x;
    const int lane  = tid & 31;
    const int wid   = tid >> 5;
    const int esub  = lane & 15;
    const int chalf = lane >> 4;
    const int cg    = chalf * 7;

    // ---- stage w transposed (once per block) ----
    for (int i = tid; i < 7168; i += 128) {
        int e = i / 14, c = i - e * 14;
        w_s[c * 512 + e] = w[i];
    }
    __syncthreads();

    // ---- fused Gram: 105 symmetric pairs split across 4 warps ----
    {
        int p = 0;
        for (int c = 0; c < 14; ++c) {
            for (int c2 = c; c2 < 14; ++c2, ++p) {
                if ((p & 3) != wid) continue;
                const float* ra = w_s + c  * 512 + 4 * lane;
                const float* rb = w_s + c2 * 512 + 4 * lane;
                float sdot = 0.0f;
                #pragma unroll
                for (int k = 0; k < 4; ++k) {
                    float4 a = *(const float4*)(ra + 128 * k);
                    float4 b = *(const float4*)(rb + 128 * k);
                    sdot += a.x * b.x + a.y * b.y + a.z * b.z + a.w * b.w;
                }
                #pragma unroll
                for (int o = 16; o; o >>= 1) sdot += __shfl_xor_sync(FULLMASK, sdot, o);
                if (lane == 0) { gram_s[c * 14 + c2] = sdot; gram_s[c2 * 14 + c] = sdot; }
            }
        }
    }
    __syncthreads();   // last block-wide sync; hot loop is warp-local

    const ull C17  = pk(1.0f / 7.0f,  1.0f / 7.0f);
    const ull C156 = pk(-1.0f / 56.0f, -1.0f / 56.0f);

    const int gwarp = blockIdx.x * 4 + wid;
    float wsum = 0.0f;

    for (int s = gwarp; s < 8192; s += 1184) {
        // y prefetch (consumed ~2000 inst later)
        const int yv = (lane < 14) ? y[s * 14 + lane] : 0;

        ull acc[7][8];
        #pragma unroll
        for (int ci = 0; ci < 7; ++ci)
            #pragma unroll
            for (int m = 0; m < 8; ++m) acc[ci][m] = 0ull;
        float l1 = 0.0f;

        const float4* xb = (const float4*)(x + (size_t)s * 4096) + 4 * esub;
        float4 q0 = xb[0], q1 = xb[1], q2 = xb[2], q3 = xb[3];

        #pragma unroll
        for (int i = 0; i < 16; ++i) {
            // pm[m] = (x[e0,m], x[e1,m])
            ull pm[8];
            pm[0] = pk(q0.x, q2.x); pm[1] = pk(q0.y, q2.y);
            pm[2] = pk(q0.z, q2.z); pm[3] = pk(q0.w, q2.w);
            pm[4] = pk(q1.x, q3.x); pm[5] = pk(q1.y, q3.y);
            pm[6] = pk(q1.z, q3.z); pm[7] = pk(q1.w, q3.w);

            // prefetch next i-step
            if (i < 15) {
                const float4* nx = xb + 64 * (i + 1);
                q0 = nx[0]; q1 = nx[1]; q2 = nx[2]; q3 = nx[3];
            }

            // l1: unbiased var over m for both e at once (packed)
            {
                ull s2 = add2(add2(add2(pm[0], pm[1]), add2(pm[2], pm[3])),
                              add2(add2(pm[4], pm[5]), add2(pm[6], pm[7])));
                ull qs = mul2(pm[0], pm[0]);
                #pragma unroll
                for (int m = 1; m < 8; ++m) qs = ffma2(pm[m], pm[m], qs);
                ull m1   = mul2(s2, s2);
                ull var2 = ffma2(m1, C156, mul2(qs, C17));
                float va, vb; upk(var2, va, vb);
                l1 += fabsf(va) + fabsf(vb);
            }

            // GEMM: 7 classes x 8 m, e-pair packed
            const int eo = 32 * i + 2 * esub;
            #pragma unroll
            for (int ci = 0; ci < 7; ++ci) {
                ull w2 = *(const ull*)(w_s + (cg + ci) * 512 + eo);
                #pragma unroll
                for (int m = 0; m < 8; ++m)
                    acc[ci][m] = ffma2(pm[m], w2, acc[ci][m]);
            }
        }

        // ---- build 64 values, 4-round merge-halve over 16-lane halves ----
        float v[64];
        #pragma unroll
        for (int ci = 0; ci < 7; ++ci)
            #pragma unroll
            for (int m = 0; m < 8; ++m) {
                float lo, hi; upk(acc[ci][m], lo, hi);
                v[ci * 8 + m] = lo + hi;
            }
        v[56] = l1;
        #pragma unroll
        for (int j = 57; j < 64; ++j) v[j] = 0.0f;

        float u32a[32];
        #pragma unroll
        for (int j = 0; j < 32; ++j) {
            bool h = (lane & 8) != 0;
            float send = h ? v[2 * j] : v[2 * j + 1];
            float keep = h ? v[2 * j + 1] : v[2 * j];
            u32a[j] = keep + __shfl_xor_sync(FULLMASK, send, 8);
        }
        float u16[16];
        #pragma unroll
        for (int j = 0; j < 16; ++j) {
            bool h = (lane & 4) != 0;
            float send = h ? u32a[2 * j] : u32a[2 * j + 1];
            float keep = h ? u32a[2 * j + 1] : u32a[2 * j];
            u16[j] = keep + __shfl_xor_sync(FULLMASK, send, 4);
        }
        float u8v[8];
        #pragma unroll
        for (int j = 0; j < 8; ++j) {
            bool h = (lane & 2) != 0;
            float send = h ? u16[2 * j] : u16[2 * j + 1];
            float keep = h ? u16[2 * j + 1] : u16[2 * j];
            u8v[j] = keep + __shfl_xor_sync(FULLMASK, send, 2);
        }
        float u4v[4];
        #pragma unroll
        for (int j = 0; j < 4; ++j) {
            bool h = (lane & 1) != 0;
            float send = h ? u8v[2 * j] : u8v[2 * j + 1];
            float keep = h ? u8v[2 * j + 1] : u8v[2 * j];
            u4v[j] = keep + __shfl_xor_sync(FULLMASK, send, 1);
        }
        // slot t holds full half-sum of value idx = t*16 + brev4(esub)
        const int bidx = __brev((unsigned)esub) >> 28;
        #pragma unroll
        for (int t = 0; t < 4; ++t) {
            int idx = t * 16 + bidx;
            if (idx < 56)      dot_s[wid][chalf * 56 + idx] = u4v[t];
            else if (idx == 56) l1_s[wid][chalf] = u4v[t];
        }
        __syncwarp();

        // ---- epilogue (warp-local) ----
        const bool inc = lane < 14;
        float dmax = -FLT_MAX;
        if (inc) {
            #pragma unroll
            for (int m = 0; m < 8; ++m)
                dmax = fmaxf(dmax, dot_s[wid][lane * 8 + m]);
            dc_s[wid][lane] = dmax;
        }
        const unsigned pmask = __ballot_sync(FULLMASK, inc && (yv == 1));
        const unsigned nmask = (~pmask) & 0x3FFFu;
        const int npos = __popc(pmask);
        const int nneg = __popc(nmask);
        __syncwarp();

        float sloc = 0.0f, diag = 0.0f, row = 0.0f;
        if (inc && ((pmask >> lane) & 1)) {
            if (nneg > 0) {
                #pragma unroll
                for (int n = 0; n < 14; ++n)
                    if ((nmask >> n) & 1) sloc += softplus_f(dc_s[wid][n] - dmax);
            } else {
                sloc = softplus_f(-dmax);
            }
            diag = gram_s[lane * 14 + lane];
            #pragma unroll
            for (int c2 = 0; c2 < 14; ++c2)
                if ((pmask >> c2) & 1) row += gram_s[lane * 14 + c2];
        }
        #pragma unroll
        for (int o = 16; o; o >>= 1) {
            sloc += __shfl_xor_sync(FULLMASK, sloc, o);
            diag += __shfl_xor_sync(FULLMASK, diag, o);
            row  += __shfl_xor_sync(FULLMASK, row,  o);
        }
        if (lane == 0) {
            const float npf = (float)npos;
            float tv = 0.0f;
            if (npos > 1) tv = (diag - row / npf) / (npf - 1.0f);
            const float base = sloc / npf;
            const float l1t = l1_s[wid][0];
            wsum += 2.0f * (0.7f * (1.0f + tv) * base + 0.3f * l1t);
        }
    }

    if (lane == 0) g_partials[gwarp] = wsum;
}

// ---------------------------------------------------------------------------
// Final deterministic reduction: 1184 partials -> mean
// ---------------------------------------------------------------------------
__global__ void reduce_kernel(float* __restrict__ out) {
    const int tid = threadIdx.x;   // 1024 threads
    float v = g_partials[tid];
    if (tid < 160) v += g_partials[1024 + tid];
    #pragma unroll
    for (int o = 16; o; o >>= 1) v += __shfl_xor_sync(FULLMASK, v, o);
    __shared__ float red[32];
    if ((tid & 31) == 0) red[tid >> 5] = v;
    __syncthreads();
    if (tid < 32) {
        float s = red[tid];
        #pragma unroll
        for (int o = 16; o; o >>= 1) s += __shfl_xor_sync(FULLMASK, s, o);
        if (tid == 0) out[0] = s * (1.0f / 8192.0f);
    }
}

extern "C" void kernel_launch(void* const* d_in, const int* in_sizes, int n_in,
                              void* d_out, int out_size) {
    const float* x = (const float*)d_in[0];
    const int*   y = (const int*)d_in[1];
    const float* w = (const float*)d_in[2];

    main_kernel<<<296, 128>>>(x, y, w);
    reduce_kernel<<<1, 1024>>>((float*)d_out);
}

// round 11
// speedup vs baseline: 1.0735x; 1.0735x over previous
#include <cuda_runtime.h>
#include <float.h>

typedef unsigned long long ull;
#define FULLMASK 0xFFFFFFFFu
#define NBLK 296
#define WSTRIDE 528   // floats per w_s row; 7*528 % 32 == 16 -> ch halves hit disjoint banks

// ---------------------------------------------------------------------------
// MID_LOSS: B=8192, E=512, M=8, C=14, BETA=0.3
// x [B, E*M] f32 (m contiguous per e), y [B,C] i32, w [E,C] f32
// One kernel. 296 blocks x 256 thr = 2368 warps, 16 warps/SM.
// Lane = (ch, mh, eslot) = (lane>>4, (lane>>3)&1, lane&7).
// Lane computes 7 classes (ch half) x 4 m (mh half), packed f32x2 over
// e-pairs (2*eslot, 2*eslot+1) + 16*i, i in [0,32).
// ---------------------------------------------------------------------------

static __device__ float g_partials[NBLK];
static __device__ unsigned g_counter = 0;

__device__ __forceinline__ ull ffma2(ull a, ull b, ull c) {
    ull d; asm("fma.rn.f32x2 %0, %1, %2, %3;" : "=l"(d) : "l"(a), "l"(b), "l"(c));
    return d;
}
__device__ __forceinline__ ull add2(ull a, ull b) {
    ull d; asm("add.rn.f32x2 %0, %1, %2;" : "=l"(d) : "l"(a), "l"(b));
    return d;
}
__device__ __forceinline__ ull mul2(ull a, ull b) {
    ull d; asm("mul.rn.f32x2 %0, %1, %2;" : "=l"(d) : "l"(a), "l"(b));
    return d;
}
__device__ __forceinline__ ull pk(float lo, float hi) {
    ull d; asm("mov.b64 %0, {%1, %2};" : "=l"(d) : "f"(lo), "f"(hi));
    return d;
}
__device__ __forceinline__ void upk(ull v, float& lo, float& hi) {
    asm("mov.b64 {%0, %1}, %2;" : "=f"(lo), "=f"(hi) : "l"(v));
}
__device__ __forceinline__ ull abs2(ull a) { return a & 0x7FFFFFFF7FFFFFFFull; }
__device__ __forceinline__ ull shfl_xor_u64(ull v, int m) {
    unsigned lo = (unsigned)v, hi = (unsigned)(v >> 32);
    lo = __shfl_xor_sync(FULLMASK, lo, m);
    hi = __shfl_xor_sync(FULLMASK, hi, m);
    return ((ull)hi << 32) | (ull)lo;
}
__device__ __forceinline__ float softplus_f(float v) {
    return fmaxf(v, 0.0f) + log1pf(expf(-fabsf(v)));
}

__global__ __launch_bounds__(256, 2)
void main_kernel(const float* __restrict__ x, const int* __restrict__ y,
                 const float* __restrict__ w, float* __restrict__ out) {
    __shared__ __align__(16) float w_s[14 * WSTRIDE];
    __shared__ float gram_s[196];
    __shared__ float dot_s[8][112];   // per-warp [c*8+m]
    __shared__ float dc_s[8][16];
    __shared__ float l1_s[8][4];
    __shared__ float wpart[8];
    __shared__ int lastflag;

    const int tid   = threadIdx.x;
    const int lane  = tid & 31;
    const int wid   = tid >> 5;
    const int eslot = lane & 7;
    const int mh    = (lane >> 3) & 1;
    const int ch    = lane >> 4;

    // ---- stage w transposed [c][e], stride 528 ----
    for (int i = tid; i < 7168; i += 256) {
        int e = i / 14, c = i - e * 14;
        w_s[c * WSTRIDE + e] = w[i];
    }
    __syncthreads();

    // ---- fused Gram: 105 symmetric pairs over 8 warps ----
    {
        int p = 0;
        for (int c = 0; c < 14; ++c)
            for (int c2 = c; c2 < 14; ++c2, ++p) {
                if ((p & 7) != wid) continue;
                const float* ra = w_s + c  * WSTRIDE + 4 * lane;
                const float* rb = w_s + c2 * WSTRIDE + 4 * lane;
                float sd = 0.0f;
                #pragma unroll
                for (int k = 0; k < 4; ++k) {
                    float4 a = *(const float4*)(ra + 128 * k);
                    float4 b = *(const float4*)(rb + 128 * k);
                    sd += a.x * b.x + a.y * b.y + a.z * b.z + a.w * b.w;
                }
                #pragma unroll
                for (int o = 16; o; o >>= 1) sd += __shfl_xor_sync(FULLMASK, sd, o);
                if (lane == 0) { gram_s[c * 14 + c2] = sd; gram_s[c2 * 14 + c] = sd; }
            }
    }
    __syncthreads();   // hot loop below is warp-local

    const ull C17  = pk( 1.0f / 7.0f,   1.0f / 7.0f);
    const ull C156 = pk(-1.0f / 56.0f, -1.0f / 56.0f);

    const int gwarp = blockIdx.x * 8 + wid;
    float wsum = 0.0f;

    for (int s = gwarp; s < 8192; s += 2368) {
        const int yv = (lane < 14) ? y[s * 14 + lane] : 0;

        ull acc[4][7];   // [mi][ci], packed over e-pair
        #pragma unroll
        for (int mi = 0; mi < 4; ++mi)
            #pragma unroll
            for (int ci = 0; ci < 7; ++ci) acc[mi][ci] = 0ull;
        ull l1acc = 0ull;

        // lane's float4 stream: f(i) = 32*i + 4*eslot + mh ; pair at +2
        const float4* xp = (const float4*)(x + (size_t)s * 4096) + 4 * eslot + mh;
        float4 qa[4], qb[4];
        #pragma unroll
        for (int j = 0; j < 4; ++j) { qa[j] = xp[32 * j]; qb[j] = xp[32 * j + 2]; }

        const char* wp = (const char*)w_s + (size_t)(ch * 7 * WSTRIDE + 2 * eslot) * 4;

        for (int ib = 0; ib < 32; ib += 4) {
            #pragma unroll
            for (int j = 0; j < 4; ++j) {
                // extract this step's packed operands (e0 in lo, e0+1 in hi)
                ull pm0 = pk(qa[j].x, qb[j].x);
                ull pm1 = pk(qa[j].y, qb[j].y);
                ull pm2 = pk(qa[j].z, qb[j].z);
                ull pm3 = pk(qa[j].w, qb[j].w);
                // refill buffer j for step ib+4+j (>=3 bodies of cover)
                if (ib + 4 < 32) {
                    const float4* np = xp + 32 * (ib + 4 + j);
                    qa[j] = np[0]; qb[j] = np[2];
                }
                // GEMM: 7 classes x 4 m
                const char* wrow = wp + (ib + j) * 64;
                #pragma unroll
                for (int ci = 0; ci < 7; ++ci) {
                    ull w2 = *(const ull*)(wrow + ci * (WSTRIDE * 4));
                    acc[0][ci] = ffma2(pm0, w2, acc[0][ci]);
                    acc[1][ci] = ffma2(pm1, w2, acc[1][ci]);
                    acc[2][ci] = ffma2(pm2, w2, acc[2][ci]);
                    acc[3][ci] = ffma2(pm3, w2, acc[3][ci]);
                }
                // l1: half-m moments, partner (mh^1) completes the m sum
                ull sh = add2(add2(pm0, pm1), add2(pm2, pm3));
                ull qh = mul2(pm0, pm0);
                qh = ffma2(pm1, pm1, qh);
                qh = ffma2(pm2, pm2, qh);
                qh = ffma2(pm3, pm3, qh);
                ull st = add2(sh, shfl_xor_u64(sh, 8));
                ull qt = add2(qh, shfl_xor_u64(qh, 8));
                ull var2 = ffma2(mul2(st, st), C156, mul2(qt, C17));
                l1acc = add2(l1acc, abs2(var2));
            }
        }

        // ---- 32-value merge-halve over eslot (offsets 4,2,1) ----
        float v[32];
        #pragma unroll
        for (int mi = 0; mi < 4; ++mi)
            #pragma unroll
            for (int ci = 0; ci < 7; ++ci) {
                float lo, hi; upk(acc[mi][ci], lo, hi);
                v[mi * 7 + ci] = lo + hi;
            }
        { float lo, hi; upk(l1acc, lo, hi); v[28] = lo + hi; }
        v[29] = 0.0f; v[30] = 0.0f; v[31] = 0.0f;

        float u16[16];
        #pragma unroll
        for (int j = 0; j < 16; ++j) {
            bool h = (lane & 4) != 0;
            float snd = h ? v[2 * j] : v[2 * j + 1];
            float kp  = h ? v[2 * j + 1] : v[2 * j];
            u16[j] = kp + __shfl_xor_sync(FULLMASK, snd, 4);
        }
        float u8v[8];
        #pragma unroll
        for (int j = 0; j < 8; ++j) {
            bool h = (lane & 2) != 0;
            float snd = h ? u16[2 * j] : u16[2 * j + 1];
            float kp  = h ? u16[2 * j + 1] : u16[2 * j];
            u8v[j] = kp + __shfl_xor_sync(FULLMASK, snd, 2);
        }
        float u4v[4];
        #pragma unroll
        for (int j = 0; j < 4; ++j) {
            bool h = (lane & 1) != 0;
            float snd = h ? u8v[2 * j] : u8v[2 * j + 1];
            float kp  = h ? u8v[2 * j + 1] : u8v[2 * j];
            u4v[j] = kp + __shfl_xor_sync(FULLMASK, snd, 1);
        }
        // slot t holds full group-sum of value idx = t*8 + brev3(eslot)
        const int bidx = __brev((unsigned)eslot) >> 29;
        #pragma unroll
        for (int t = 0; t < 4; ++t) {
            int idx = t * 8 + bidx;
            if (idx < 28) {
                int mi = idx / 7, ci = idx - mi * 7;
                dot_s[wid][(ch * 7 + ci) * 8 + (mh * 4 + mi)] = u4v[t];
            } else if (idx == 28) {
                l1_s[wid][ch * 2 + mh] = u4v[t];
            }
        }
        __syncwarp();

        // ---- epilogue (warp-local) ----
        const bool inc = lane < 14;
        float dmax = -FLT_MAX;
        if (inc) {
            #pragma unroll
            for (int m = 0; m < 8; ++m)
                dmax = fmaxf(dmax, dot_s[wid][lane * 8 + m]);
            dc_s[wid][lane] = dmax;
        }
        const unsigned pmask = __ballot_sync(FULLMASK, inc && (yv == 1));
        const unsigned nmask = (~pmask) & 0x3FFFu;
        const int npos = __popc(pmask);
        const int nneg = __popc(nmask);
        __syncwarp();

        float sloc = 0.0f, diag = 0.0f, row = 0.0f;
        if (inc && ((pmask >> lane) & 1)) {
            if (nneg > 0) {
                #pragma unroll
                for (int n = 0; n < 14; ++n)
                    if ((nmask >> n) & 1) sloc += softplus_f(dc_s[wid][n] - dmax);
            } else {
                sloc = softplus_f(-dmax);
            }
            diag = gram_s[lane * 15];
            #pragma unroll
            for (int c2 = 0; c2 < 14; ++c2)
                if ((pmask >> c2) & 1) row += gram_s[lane * 14 + c2];
        }
        #pragma unroll
        for (int o = 16; o; o >>= 1) {
            sloc += __shfl_xor_sync(FULLMASK, sloc, o);
            diag += __shfl_xor_sync(FULLMASK, diag, o);
            row  += __shfl_xor_sync(FULLMASK, row,  o);
        }
        if (lane == 0) {
            const float npf = (float)npos;
            float tv = 0.0f;
            if (npos > 1) tv = (diag - row / npf) / (npf - 1.0f);
            const float base = sloc / npf;
            const float l1t = 0.25f * (l1_s[wid][0] + l1_s[wid][1]
                                     + l1_s[wid][2] + l1_s[wid][3]);
            wsum += 2.0f * (0.7f * (1.0f + tv) * base + 0.3f * l1t);
        }
    }

    // ---- block partial + in-kernel final reduction (last block) ----
    if (lane == 0) wpart[wid] = wsum;
    __syncthreads();
    if (tid == 0) {
        float bs = wpart[0] + wpart[1] + wpart[2] + wpart[3]
                 + wpart[4] + wpart[5] + wpart[6] + wpart[7];
        g_partials[blockIdx.x] = bs;
        __threadfence();
        unsigned old = atomicAdd(&g_counter, 1u);
        lastflag = (old == NBLK - 1) ? 1 : 0;
    }
    __syncthreads();
    if (lastflag && wid == 0) {
        float vsum = 0.0f;
        for (int k = lane; k < NBLK; k += 32) vsum += __ldcg(&g_partials[k]);
        #pragma unroll
        for (int o = 16; o; o >>= 1) vsum += __shfl_xor_sync(FULLMASK, vsum, o);
        if (lane == 0) {
            out[0] = vsum * (1.0f / 8192.0f);
            g_counter = 0;   // reset for next graph replay
        }
    }
}

extern "C" void kernel_launch(void* const* d_in, const int* in_sizes, int n_in,
                              void* d_out, int out_size) {
    const float* x = (const float*)d_in[0];
    const int*   y = (const int*)d_in[1];
    const float* w = (const float*)d_in[2];

    main_kernel<<<NBLK, 256>>>(x, y, w, (float*)d_out);
}

// round 13
// speedup vs baseline: 1.7226x; 1.6046x over previous
#include <cuda_runtime.h>
#include <float.h>

typedef unsigned long long ull;
#define FULLMASK 0xFFFFFFFFu
#define NBLK 296
#define WROW 516   // float2 per w_d row (pad 4 -> bank-clean LDS.64)

// ---------------------------------------------------------------------------
// MID_LOSS: B=8192, E=512, M=8, C=14, BETA=0.3
// x [B, E*M] f32 (m contiguous per e), y [B,C] i32, w [E,C] f32
// One kernel, warp-autonomous. 296 blocks x 256 thr.
// Lane = (ch, es): ch = lane>>4 owns classes ch*7..ch*7+6;
// es = lane&15 owns embeds e = es + 16*i, i in [0,32)  (FULL m per lane).
// Accumulators packed over m-pairs: acc[ci][mp], mp=(m0,m1)..(m6,m7).
// x float4 components are natively the packed pairs (loaded as longlong2).
// w duplicated (w,w) in dynamic smem -> FFMA2 B-operand is one LDS.64.
// ---------------------------------------------------------------------------

static __device__ float g_partials[NBLK];
static __device__ unsigned g_counter = 0;

__device__ __forceinline__ ull ffma2(ull a, ull b, ull c) {
    ull d; asm("fma.rn.f32x2 %0, %1, %2, %3;" : "=l"(d) : "l"(a), "l"(b), "l"(c));
    return d;
}
__device__ __forceinline__ ull add2(ull a, ull b) {
    ull d; asm("add.rn.f32x2 %0, %1, %2;" : "=l"(d) : "l"(a), "l"(b));
    return d;
}
__device__ __forceinline__ ull mul2(ull a, ull b) {
    ull d; asm("mul.rn.f32x2 %0, %1, %2;" : "=l"(d) : "l"(a), "l"(b));
    return d;
}
__device__ __forceinline__ void upk(ull v, float& lo, float& hi) {
    asm("mov.b64 {%0, %1}, %2;" : "=f"(lo), "=f"(hi) : "l"(v));
}
__device__ __forceinline__ float softplus_f(float v) {
    return fmaxf(v, 0.0f) + log1pf(expf(-fabsf(v)));
}

__global__ __launch_bounds__(256, 2)
void main_kernel(const float* __restrict__ x, const int* __restrict__ y,
                 const float* __restrict__ w, float* __restrict__ out) {
    extern __shared__ __align__(16) float2 w_d[];   // [14][WROW], (w,w) pairs
    __shared__ float gram_s[196];
    __shared__ float dot_s[8][112];   // per-warp [c*8+m]
    __shared__ float dc_s[8][16];
    __shared__ float l1_s[8][2];
    __shared__ float wpart[8];
    __shared__ int lastflag;

    const int tid  = threadIdx.x;
    const int lane = tid & 31;
    const int wid  = tid >> 5;
    const int es   = lane & 15;
    const int ch   = lane >> 4;

    // ---- stage w duplicated: w_d[c][e] = (w[e,c], w[e,c]) ----
    for (int i = tid; i < 7168; i += 256) {
        int e = i / 14, c = i - e * 14;
        float v = w[i];
        w_d[c * WROW + e] = make_float2(v, v);
    }
    __syncthreads();

    // ---- fused Gram: 105 symmetric pairs over 8 warps ----
    {
        int p = 0;
        for (int c = 0; c < 14; ++c)
            for (int c2 = c; c2 < 14; ++c2, ++p) {
                if ((p & 7) != wid) continue;
                float sd = 0.0f;
                #pragma unroll
                for (int k = 0; k < 16; ++k) {
                    int e = lane + 32 * k;
                    sd += w_d[c * WROW + e].x * w_d[c2 * WROW + e].x;
                }
                #pragma unroll
                for (int o = 16; o; o >>= 1) sd += __shfl_xor_sync(FULLMASK, sd, o);
                if (lane == 0) { gram_s[c * 14 + c2] = sd; gram_s[c2 * 14 + c] = sd; }
            }
    }
    __syncthreads();   // hot loop below is warp-local

    const int gwarp = blockIdx.x * 8 + wid;
    float wsum = 0.0f;

    for (int s = gwarp; s < 8192; s += 2368) {
        const int yv = (lane < 14) ? y[s * 14 + lane] : 0;

        ull acc[7][4];   // [ci][m-pair]
        #pragma unroll
        for (int ci = 0; ci < 7; ++ci)
            #pragma unroll
            for (int mp = 0; mp < 4; ++mp) acc[ci][mp] = 0ull;
        float l1 = 0.0f;

        // lane's stream: per step i, embed e = es + 16i -> 32B at float4 idx 2e
        const longlong2* xp = (const longlong2*)(x + (size_t)s * 4096) + 2 * es;
        longlong2 qa[4], qb[4];   // qa=(m0..3), qb=(m4..7), depth-4 pipeline
        #pragma unroll
        for (int j = 0; j < 4; ++j) { qa[j] = xp[32 * j]; qb[j] = xp[32 * j + 1]; }

        const float2* wp = w_d + ch * 7 * WROW + es;

        for (int ib = 0; ib < 32; ib += 4) {
            #pragma unroll
            for (int j = 0; j < 4; ++j) {
                const ull p0 = (ull)qa[j].x;   // (m0,m1)
                const ull p1 = (ull)qa[j].y;   // (m2,m3)
                const ull p2 = (ull)qb[j].x;   // (m4,m5)
                const ull p3 = (ull)qb[j].y;   // (m6,m7)
                // refill slot j for step ib+4+j
                if (ib + 4 < 32) {
                    qa[j] = xp[32 * (ib + 4 + j)];
                    qb[j] = xp[32 * (ib + 4 + j) + 1];
                }
                // GEMM: 7 classes, duplicated-w LDS.64 operand
                const float2* wrow = wp + (ib + j) * 16;
                #pragma unroll
                for (int ci = 0; ci < 7; ++ci) {
                    ull w2 = *(const ull*)(wrow + ci * WROW);
                    acc[ci][0] = ffma2(p0, w2, acc[ci][0]);
                    acc[ci][1] = ffma2(p1, w2, acc[ci][1]);
                    acc[ci][2] = ffma2(p2, w2, acc[ci][2]);
                    acc[ci][3] = ffma2(p3, w2, acc[ci][3]);
                }
                // l1: unbiased var over the 8 m's of this e (lane-local, no shfl)
                ull sh = add2(add2(p0, p1), add2(p2, p3));
                ull qh = mul2(p0, p0);
                qh = ffma2(p1, p1, qh);
                qh = ffma2(p2, p2, qh);
                qh = ffma2(p3, p3, qh);
                float slo, shi; upk(sh, slo, shi);
                float qlo, qhi; upk(qh, qlo, qhi);
                const float se = slo + shi;
                const float qe = qlo + qhi;
                const float var = fmaf(se * se, -1.0f / 56.0f, qe * (1.0f / 7.0f));
                l1 += fabsf(var);
            }
        }

        // ---- 64-value merge-halve over the 16-lane ch group ----
        float v64[64];
        #pragma unroll
        for (int ci = 0; ci < 7; ++ci)
            #pragma unroll
            for (int mp = 0; mp < 4; ++mp)
                upk(acc[ci][mp], v64[(ci * 4 + mp) * 2], v64[(ci * 4 + mp) * 2 + 1]);
        v64[56] = l1;
        #pragma unroll
        for (int j = 57; j < 64; ++j) v64[j] = 0.0f;

        float u32a[32];
        #pragma unroll
        for (int j = 0; j < 32; ++j) {
            bool h = (lane & 8) != 0;
            float snd = h ? v64[2 * j] : v64[2 * j + 1];
            float kp  = h ? v64[2 * j + 1] : v64[2 * j];
            u32a[j] = kp + __shfl_xor_sync(FULLMASK, snd, 8);
        }
        float u16[16];
        #pragma unroll
        for (int j = 0; j < 16; ++j) {
            bool h = (lane & 4) != 0;
            float snd = h ? u32a[2 * j] : u32a[2 * j + 1];
            float kp  = h ? u32a[2 * j + 1] : u32a[2 * j];
            u16[j] = kp + __shfl_xor_sync(FULLMASK, snd, 4);
        }
        float u8v[8];
        #pragma unroll
        for (int j = 0; j < 8; ++j) {
            bool h = (lane & 2) != 0;
            float snd = h ? u16[2 * j] : u16[2 * j + 1];
            float kp  = h ? u16[2 * j + 1] : u16[2 * j];
            u8v[j] = kp + __shfl_xor_sync(FULLMASK, snd, 2);
        }
        float u4v[4];
        #pragma unroll
        for (int j = 0; j < 4; ++j) {
            bool h = (lane & 1) != 0;
            float snd = h ? u8v[2 * j] : u8v[2 * j + 1];
            float kp  = h ? u8v[2 * j + 1] : u8v[2 * j];
            u4v[j] = kp + __shfl_xor_sync(FULLMASK, snd, 1);
        }
        // slot t at lane holds full group-sum of value idx = t*16 + brev4(es)
        const int bidx = __brev((unsigned)es) >> 28;
        #pragma unroll
        for (int t = 0; t < 4; ++t) {
            int idx = t * 16 + bidx;
            if (idx < 56) {
                int k = idx >> 1;
                int ci = k >> 2, mp = k & 3;
                int m = 2 * mp + (idx & 1);
                dot_s[wid][(ch * 7 + ci) * 8 + m] = u4v[t];
            } else if (idx == 56) {
                l1_s[wid][ch] = u4v[t];
            }
        }
        __syncwarp();

        // ---- epilogue (warp-local) ----
        const bool inc = lane < 14;
        float dmax = -FLT_MAX;
        if (inc) {
            #pragma unroll
            for (int m = 0; m < 8; ++m)
                dmax = fmaxf(dmax, dot_s[wid][lane * 8 + m]);
            dc_s[wid][lane] = dmax;
        }
        const unsigned pmask = __ballot_sync(FULLMASK, inc && (yv == 1));
        const unsigned nmask = (~pmask) & 0x3FFFu;
        const int npos = __popc(pmask);
        const int nneg = __popc(nmask);
        __syncwarp();

        float sloc = 0.0f, diag = 0.0f, row = 0.0f;
        if (inc && ((pmask >> lane) & 1)) {
            if (nneg > 0) {
                #pragma unroll
                for (int n = 0; n < 14; ++n)
                    if ((nmask >> n) & 1) sloc += softplus_f(dc_s[wid][n] - dmax);
            } else {
                sloc = softplus_f(-dmax);
            }
            diag = gram_s[lane * 15];
            #pragma unroll
            for (int c2 = 0; c2 < 14; ++c2)
                if ((pmask >> c2) & 1) row += gram_s[lane * 14 + c2];
        }
        #pragma unroll
        for (int o = 16; o; o >>= 1) {
            sloc += __shfl_xor_sync(FULLMASK, sloc, o);
            diag += __shfl_xor_sync(FULLMASK, diag, o);
            row  += __shfl_xor_sync(FULLMASK, row,  o);
        }
        if (lane == 0) {
            const float npf = (float)npos;
            float tv = 0.0f;
            if (npos > 1) tv = (diag - row / npf) / (npf - 1.0f);
            const float base = sloc / npf;
            const float l1t = l1_s[wid][0];
            wsum += 2.0f * (0.7f * (1.0f + tv) * base + 0.3f * l1t);
        }
    }

    // ---- block partial + in-kernel final reduction (last block) ----
    if (lane == 0) wpart[wid] = wsum;
    __syncthreads();
    if (tid == 0) {
        float bs = wpart[0] + wpart[1] + wpart[2] + wpart[3]
                 + wpart[4] + wpart[5] + wpart[6] + wpart[7];
        g_partials[blockIdx.x] = bs;
        __threadfence();
        unsigned old = atomicAdd(&g_counter, 1u);
        lastflag = (old == NBLK - 1) ? 1 : 0;
    }
    __syncthreads();
    if (lastflag && wid == 0) {
        float vsum = 0.0f;
        for (int k = lane; k < NBLK; k += 32) vsum += __ldcg(&g_partials[k]);
        #pragma unroll
        for (int o = 16; o; o >>= 1) vsum += __shfl_xor_sync(FULLMASK, vsum, o);
        if (lane == 0) {
            out[0] = vsum * (1.0f / 8192.0f);
            g_counter = 0;   // reset for next graph replay
        }
    }
}

extern "C" void kernel_launch(void* const* d_in, const int* in_sizes, int n_in,
                              void* d_out, int out_size) {
    const float* x = (const float*)d_in[0];
    const int*   y = (const int*)d_in[1];
    const float* w = (const float*)d_in[2];

    const int dyn_smem = 14 * WROW * (int)sizeof(float2);   // 57,792 B
    cudaFuncSetAttribute(main_kernel, cudaFuncAttributeMaxDynamicSharedMemorySize,
                         dyn_smem);
    main_kernel<<<NBLK, 256, dyn_smem>>>(x, y, w, (float*)d_out);
}